// round 2
// baseline (speedup 1.0000x reference)
#include <cuda_runtime.h>
#include <cstdint>

#define N_NODES 100000
#define N_EDGES 1600000
#define IN_F    512
#define OUT_F   64

#define SCAN_BLOCKS 391   // ceil(100000/256)

// ---- scratch (__device__ globals; no allocation allowed) -------------------
__device__ float g_h[(size_t)N_NODES * OUT_F];   // projected features, 25.6 MB
__device__ int   g_cnt[N_NODES];                  // histogram / cursor / degree
__device__ int   g_off[N_NODES];                  // CSR row offsets (exclusive)
__device__ int   g_bsum[512];                     // scan block sums
__device__ int   g_csr_src[N_EDGES];              // CSR: src per slot
__device__ float g_csr_w[N_EDGES];                // CSR: weight per slot

// ---------------------------------------------------------------------------
// packed f32x2 FMA (Blackwell dual-rate fp32)
// ---------------------------------------------------------------------------
__device__ __forceinline__ void ffma2(unsigned long long& d,
                                      unsigned long long a,
                                      unsigned long long b) {
    asm("fma.rn.f32x2 %0, %1, %2, %0;" : "+l"(d) : "l"(a), "l"(b));
}
__device__ __forceinline__ void unpack2(float& lo, float& hi, unsigned long long v) {
    asm("mov.b64 {%0, %1}, %2;" : "=f"(lo), "=f"(hi) : "l"(v));
}

// ---------------------------------------------------------------------------
// 0) zero histogram counters
// ---------------------------------------------------------------------------
__global__ void zero_cnt_kernel() {
    int i = blockIdx.x * blockDim.x + threadIdx.x;
    if (i < N_NODES) g_cnt[i] = 0;
}

// ---------------------------------------------------------------------------
// 1) GEMM: g_h[100000,64] = feat[100000,512] @ W[512,64]
//    64x64 tile, BK=16, 256 threads. Inner loop in fma.rn.f32x2:
//    accumulators packed along M, B pre-duplicated in SMEM ({b,b} pairs).
// ---------------------------------------------------------------------------
__global__ __launch_bounds__(256) void gemm_kernel(
    const float* __restrict__ feat, const float* __restrict__ W)
{
    __shared__ float As[16][64];     // As[k][m]
    __shared__ float Bs2[16][128];   // Bs2[k][2n..2n+1] = {W[k][n], W[k][n]}

    const int tid = threadIdx.x;
    const int m0  = blockIdx.x * 64;
    const int tx  = tid & 15;        // n-tile (4 cols each)
    const int ty  = tid >> 4;        // m-tile (4 rows each)

    // feat loader: 64 rows x 16 k, float4 per thread
    const int lr = tid >> 2;
    const int lc = (tid & 3) * 4;
    // weight loader: 16 k x 64 n, float4 per thread, duplicated on store
    const int kw = tid >> 4;
    const int nw = (tid & 15) * 4;

    unsigned long long acc[2][4];
    #pragma unroll
    for (int i = 0; i < 2; i++)
        #pragma unroll
        for (int j = 0; j < 4; j++) acc[i][j] = 0ull;  // {0.f,0.f}

    for (int k0 = 0; k0 < IN_F; k0 += 16) {
        float4 fa = make_float4(0.f, 0.f, 0.f, 0.f);
        const int row = m0 + lr;
        if (row < N_NODES)
            fa = *reinterpret_cast<const float4*>(feat + (size_t)row * IN_F + k0 + lc);
        As[lc + 0][lr] = fa.x;
        As[lc + 1][lr] = fa.y;
        As[lc + 2][lr] = fa.z;
        As[lc + 3][lr] = fa.w;

        float4 wv = *reinterpret_cast<const float4*>(W + (size_t)(k0 + kw) * OUT_F + nw);
        float4 d0 = make_float4(wv.x, wv.x, wv.y, wv.y);
        float4 d1 = make_float4(wv.z, wv.z, wv.w, wv.w);
        *reinterpret_cast<float4*>(&Bs2[kw][nw * 2])     = d0;
        *reinterpret_cast<float4*>(&Bs2[kw][nw * 2 + 4]) = d1;

        __syncthreads();

        #pragma unroll
        for (int k = 0; k < 16; k++) {
            const ulonglong2 av  = *reinterpret_cast<const ulonglong2*>(&As[k][ty * 4]);
            const ulonglong2 bv0 = *reinterpret_cast<const ulonglong2*>(&Bs2[k][tx * 8]);
            const ulonglong2 bv1 = *reinterpret_cast<const ulonglong2*>(&Bs2[k][tx * 8 + 4]);
            ffma2(acc[0][0], av.x, bv0.x);
            ffma2(acc[0][1], av.x, bv0.y);
            ffma2(acc[0][2], av.x, bv1.x);
            ffma2(acc[0][3], av.x, bv1.y);
            ffma2(acc[1][0], av.y, bv0.x);
            ffma2(acc[1][1], av.y, bv0.y);
            ffma2(acc[1][2], av.y, bv1.x);
            ffma2(acc[1][3], av.y, bv1.y);
        }
        __syncthreads();
    }

    const int rbase = m0 + ty * 4;
    #pragma unroll
    for (int mp = 0; mp < 2; mp++) {
        float lo[4], hi[4];
        #pragma unroll
        for (int n = 0; n < 4; n++) unpack2(lo[n], hi[n], acc[mp][n]);
        const int r0 = rbase + mp * 2;
        if (r0 < N_NODES)
            *reinterpret_cast<float4*>(g_h + (size_t)r0 * OUT_F + tx * 4) =
                make_float4(lo[0], lo[1], lo[2], lo[3]);
        if (r0 + 1 < N_NODES)
            *reinterpret_cast<float4*>(g_h + (size_t)(r0 + 1) * OUT_F + tx * 4) =
                make_float4(hi[0], hi[1], hi[2], hi[3]);
    }
}

// ---------------------------------------------------------------------------
// 2) CSR build: histogram -> 2-level exclusive scan -> scatter
// ---------------------------------------------------------------------------
__global__ void hist_kernel(const int* __restrict__ dst) {
    int e = blockIdx.x * blockDim.x + threadIdx.x;
    if (e < N_EDGES) atomicAdd(&g_cnt[__ldg(dst + e)], 1);
}

__global__ void scan_a_kernel() {   // per-block exclusive scan + block sum
    __shared__ int s[256];
    const int i = blockIdx.x * 256 + threadIdx.x;
    const int v = (i < N_NODES) ? g_cnt[i] : 0;
    s[threadIdx.x] = v;
    #pragma unroll
    for (int off = 1; off < 256; off <<= 1) {
        __syncthreads();
        int t = (threadIdx.x >= off) ? s[threadIdx.x - off] : 0;
        __syncthreads();
        s[threadIdx.x] += t;
    }
    if (i < N_NODES) g_off[i] = s[threadIdx.x] - v;   // exclusive
    if (threadIdx.x == 255) g_bsum[blockIdx.x] = s[255];
}

__global__ void scan_b_kernel() {   // 1 block: exclusive scan of block sums
    __shared__ int s[512];
    const int t = threadIdx.x;
    const int v = (t < SCAN_BLOCKS) ? g_bsum[t] : 0;
    s[t] = v;
    #pragma unroll
    for (int off = 1; off < 512; off <<= 1) {
        __syncthreads();
        int u = (t >= off) ? s[t - off] : 0;
        __syncthreads();
        s[t] += u;
    }
    if (t < SCAN_BLOCKS) g_bsum[t] = s[t] - v;        // exclusive
}

__global__ void scan_c_kernel() {   // add block bases; reset counters
    const int i = blockIdx.x * 256 + threadIdx.x;
    if (i < N_NODES) {
        g_off[i] += g_bsum[blockIdx.x];
        g_cnt[i] = 0;
    }
}

__global__ void scatter_kernel(const int* __restrict__ src,
                               const int* __restrict__ dst,
                               const float* __restrict__ ew) {
    int e = blockIdx.x * blockDim.x + threadIdx.x;
    if (e >= N_EDGES) return;
    const int d = __ldg(dst + e);
    const int pos = g_off[d] + atomicAdd(&g_cnt[d], 1);
    g_csr_src[pos] = __ldg(src + e);
    g_csr_w[pos]   = __ldg(ew + e);
}

// ---------------------------------------------------------------------------
// 3) Aggregate + finalize fused: 64 threads per node (one per out column).
//    out[v][c] = relu( (deg>0 ? sum(h[src][c]*w)/deg : 0) + bias[c] )
// ---------------------------------------------------------------------------
__global__ __launch_bounds__(256) void aggregate_kernel(
    float* __restrict__ out, const float* __restrict__ bias)
{
    const int tid = threadIdx.x;
    const int v   = blockIdx.x * 4 + (tid >> 6);
    const int c   = tid & 63;
    if (v >= N_NODES) return;

    const int beg = g_off[v];
    const int len = g_cnt[v];

    float acc = 0.0f;
    int j = 0;
    for (; j + 2 <= len; j += 2) {
        const int   s0 = __ldg(g_csr_src + beg + j);
        const int   s1 = __ldg(g_csr_src + beg + j + 1);
        const float w0 = __ldg(g_csr_w + beg + j);
        const float w1 = __ldg(g_csr_w + beg + j + 1);
        const float h0 = __ldg(g_h + (size_t)s0 * OUT_F + c);
        const float h1 = __ldg(g_h + (size_t)s1 * OUT_F + c);
        acc = fmaf(h0, w0, acc);
        acc = fmaf(h1, w1, acc);
    }
    if (j < len) {
        const int   s0 = __ldg(g_csr_src + beg + j);
        const float w0 = __ldg(g_csr_w + beg + j);
        acc = fmaf(__ldg(g_h + (size_t)s0 * OUT_F + c), w0, acc);
    }

    float val = (len > 0) ? (acc / (float)len) : 0.0f;
    val += __ldg(bias + c);
    out[(size_t)v * OUT_F + c] = fmaxf(val, 0.0f);
}

// ---------------------------------------------------------------------------
extern "C" void kernel_launch(void* const* d_in, const int* in_sizes, int n_in,
                              void* d_out, int out_size)
{
    const float* feat     = (const float*)d_in[0];
    const float* edge_w   = (const float*)d_in[1];
    const float* weight   = (const float*)d_in[2];
    const float* bias     = (const float*)d_in[3];
    const int*   edge_src = (const int*)d_in[4];
    const int*   edge_dst = (const int*)d_in[5];
    float* out = (float*)d_out;

    zero_cnt_kernel<<<SCAN_BLOCKS, 256>>>();
    gemm_kernel<<<(N_NODES + 63) / 64, 256>>>(feat, weight);
    hist_kernel<<<N_EDGES / 256, 256>>>(edge_dst);
    scan_a_kernel<<<SCAN_BLOCKS, 256>>>();
    scan_b_kernel<<<1, 512>>>();
    scan_c_kernel<<<SCAN_BLOCKS, 256>>>();
    scatter_kernel<<<N_EDGES / 256, 256>>>(edge_src, edge_dst, edge_w);
    aggregate_kernel<<<(N_NODES + 3) / 4, 256>>>(out, bias);
}